// round 16
// baseline (speedup 1.0000x reference)
#include <cuda_runtime.h>
#include <cuda_bf16.h>
#include <cstdint>

#define MDIM 4096
#define NDIM 4096
#define KDIM 4096

// ---------------- device scratch (no allocations allowed) ----------------
__device__ unsigned g_amax[2];                                        // float bits
__device__ __align__(128) unsigned short g_qa[(size_t)MDIM * KDIM];   // lhs quantized ints as bf16, [M][K]
__device__ __align__(128) unsigned short g_qb[(size_t)KDIM * NDIM];   // rhs quantized ints as bf16, [K][N]

// ---------------- calibration ----------------
// One launch covers BOTH tensors: blocks [0, half) -> lhs, [half, 2*half) -> rhs.
// Plain sequential grid-stride: empirically the fastest-coexisting pattern
// (strided/multi-accumulator variants flipped the pipeline into a ~645us regime).
__global__ void amax2_kernel(const float* __restrict__ lhs,
                             const float* __restrict__ rhs, int n4each) {
    const int half = gridDim.x >> 1;
    const int which = blockIdx.x >= half;
    const float* __restrict__ x = which ? rhs : lhs;
    const int bid = blockIdx.x - which * half;

    float m = 0.0f;
    const int stride = half * blockDim.x;
    for (int i = bid * blockDim.x + threadIdx.x; i < n4each; i += stride) {
        float4 v = reinterpret_cast<const float4*>(x)[i];
        m = fmaxf(m, fmaxf(fmaxf(fabsf(v.x), fabsf(v.y)), fmaxf(fabsf(v.z), fabsf(v.w))));
    }
#pragma unroll
    for (int o = 16; o > 0; o >>= 1)
        m = fmaxf(m, __shfl_xor_sync(0xFFFFFFFFu, m, o));
    if ((threadIdx.x & 31) == 0)
        atomicMax(&g_amax[which], __float_as_uint(m));  // m >= 0: uint order == float order
}

__device__ __forceinline__ float get_scale(int which) {
    float amax = __uint_as_float(g_amax[which]);
    return 127.0f / fmaxf(amax, 1e-12f);
}

// quantize to int on the int8 grid, return EXACT bf16 representation (|v|<=127)
__device__ __forceinline__ unsigned short q8_bf16(float x, float s) {
    float r = rintf(x * s);  // round-half-even, matches jnp.round
    r = fmaxf(-127.0f, fminf(127.0f, r));
    return __bfloat16_as_ushort(__float2bfloat16_rn(r));   // ints <=127 exact in bf16
}

// One launch quantizes BOTH tensors; 4 consecutive float4 per thread.
__global__ void quant2_kernel(const float* __restrict__ lhs,
                              const float* __restrict__ rhs) {
    const int half = gridDim.x >> 1;
    const int which = blockIdx.x >= half;
    const float* __restrict__ x = which ? rhs : lhs;
    unsigned short* __restrict__ q = which ? g_qb : g_qa;
    const int bid = blockIdx.x - which * half;

    float s = get_scale(which);
    int base = (bid * blockDim.x + threadIdx.x) * 4;
#pragma unroll
    for (int j = 0; j < 4; j++) {
        int idx = base + j;
        float4 v = reinterpret_cast<const float4*>(x)[idx];
        uint2 o;
        o.x = (uint32_t)q8_bf16(v.x, s) | ((uint32_t)q8_bf16(v.y, s) << 16);
        o.y = (uint32_t)q8_bf16(v.z, s) | ((uint32_t)q8_bf16(v.w, s) << 16);
        reinterpret_cast<uint2*>(q)[idx] = o;
    }
}

// ---------------- bf16 HMMA GEMM ----------------
// CTA tile 256x128 (MxN), K-chunk 64, 4-stage cp.async ring, 8 warps (4Mx2N),
// warp tile 64x64, register-fragment double buffering. Pipe/power-bound at the
// legacy mma.sync HMMA floor for plain-target sm_103.
#define NSTG 4
#define A_ST_BYTES 32768                 // 256 rows * 128B
#define STAGE_BYTES 49152                // A 32KB + B 16KB
#define GEMM_SMEM (NSTG * STAGE_BYTES)   // 196608
#define NC (KDIM / 64)

__device__ __forceinline__ uint32_t smem_u32(const void* p) {
    uint32_t a;
    asm("{ .reg .u64 t; cvta.to.shared.u64 t, %1; cvt.u32.u64 %0, t; }" : "=r"(a) : "l"(p));
    return a;
}

__global__ void __launch_bounds__(256, 1) gemm_bf16_kernel(float* __restrict__ out) {
    extern __shared__ char sm[];
    const uint32_t sb = smem_u32(sm);

    const int tid  = threadIdx.x;
    const int lane = tid & 31;
    const int warp = tid >> 5;
    const int wm = warp & 3;               // 4 warps along M (64 rows each)
    const int wn = warp >> 2;              // 2 warps along N (64 cols each)
    const int lg = lane >> 2;              // groupID
    const int lt = lane & 3;               // threadID in group

    const int mBase = blockIdx.y * 256;
    const int nBase = blockIdx.x * 128;

    float acc[4][8][4];
#pragma unroll
    for (int mi = 0; mi < 4; mi++)
#pragma unroll
        for (int ni = 0; ni < 8; ni++)
#pragma unroll
            for (int r = 0; r < 4; r++) acc[mi][ni][r] = 0.0f;

    const int a_row_in = lane & 15;
    const int a_hi = lane >> 4;

    auto issue = [&](int ch) {
        if (ch < NC) {
            const int kt = ch * 64;
            const uint32_t st = sb + (ch % NSTG) * STAGE_BYTES;
#pragma unroll
            for (int it = 0; it < 8; it++) {
                int c = tid + it * 256;
                int row = c >> 3, cb = c & 7;
                uint32_t dst = st + row * 128 + ((cb ^ (row & 7)) << 4);
                const void* src = g_qa + (size_t)(mBase + row) * KDIM + kt + cb * 8;
                asm volatile("cp.async.cg.shared.global [%0], [%1], 16;"
                             :: "r"(dst), "l"(src) : "memory");
            }
#pragma unroll
            for (int it = 0; it < 4; it++) {
                int c = tid + it * 256;
                int row = c >> 4, cb = c & 15;
                uint32_t dst = st + A_ST_BYTES + row * 256 + ((cb ^ (row & 7)) << 4);
                const void* src = g_qb + (size_t)(kt + row) * NDIM + nBase + cb * 8;
                asm volatile("cp.async.cg.shared.global [%0], [%1], 16;"
                             :: "r"(dst), "l"(src) : "memory");
            }
        }
        asm volatile("cp.async.commit_group;" ::: "memory");
    };

    auto ldA = [&](uint32_t stA, int ks, uint32_t a[4][4]) {
#pragma unroll
        for (int mi = 0; mi < 4; mi++) {
            int row = wm * 64 + mi * 16 + a_row_in;
            int cb  = ks * 2 + a_hi;
            uint32_t addr = stA + row * 128 + ((cb ^ (row & 7)) << 4);
            asm volatile("ldmatrix.sync.aligned.m8n8.x4.shared.b16 {%0,%1,%2,%3}, [%4];"
                         : "=r"(a[mi][0]), "=r"(a[mi][1]), "=r"(a[mi][2]), "=r"(a[mi][3])
                         : "r"(addr));
        }
    };
    auto ldB = [&](uint32_t stB, int ks, uint32_t b[4][4]) {
#pragma unroll
        for (int p = 0; p < 4; p++) {
            int krow = ks * 16 + a_row_in;
            int cb   = (wn * 8 + p * 2) + a_hi;
            uint32_t addr = stB + krow * 256 + ((cb ^ (krow & 7)) << 4);
            asm volatile("ldmatrix.sync.aligned.m8n8.x4.trans.shared.b16 {%0,%1,%2,%3}, [%4];"
                         : "=r"(b[p][0]), "=r"(b[p][1]), "=r"(b[p][2]), "=r"(b[p][3])
                         : "r"(addr));
        }
    };

    issue(0); issue(1); issue(2);

    uint32_t afrag[2][4][4], bfrag[2][4][4];

    for (int ch = 0; ch < NC; ch++) {
        asm volatile("cp.async.wait_group 2;" ::: "memory");
        __syncthreads();
        issue(ch + 3);

        const uint32_t stA = sb + (ch % NSTG) * STAGE_BYTES;
        const uint32_t stB = stA + A_ST_BYTES;

        ldA(stA, 0, afrag[0]);
        ldB(stB, 0, bfrag[0]);

#pragma unroll
        for (int ks = 0; ks < 4; ks++) {
            const int cur = ks & 1, nxt = cur ^ 1;
            if (ks < 3) {
                ldA(stA, ks + 1, afrag[nxt]);
                ldB(stB, ks + 1, bfrag[nxt]);
            }
#pragma unroll
            for (int p = 0; p < 4; p++) {
#pragma unroll
                for (int h = 0; h < 2; h++) {
                    int ni = p * 2 + h;
#pragma unroll
                    for (int mi = 0; mi < 4; mi++) {
                        asm volatile(
                            "mma.sync.aligned.m16n8k16.row.col.f32.bf16.bf16.f32 "
                            "{%0,%1,%2,%3}, {%4,%5,%6,%7}, {%8,%9}, {%0,%1,%2,%3};\n"
                            : "+f"(acc[mi][ni][0]), "+f"(acc[mi][ni][1]),
                              "+f"(acc[mi][ni][2]), "+f"(acc[mi][ni][3])
                            : "r"(afrag[cur][mi][0]), "r"(afrag[cur][mi][1]),
                              "r"(afrag[cur][mi][2]), "r"(afrag[cur][mi][3]),
                              "r"(bfrag[cur][p][2 * h]), "r"(bfrag[cur][p][2 * h + 1]));
                    }
                }
            }
        }
    }

    // ---------------- epilogue: exact fp32 dequant ----------------
    float inv = 1.0f / (get_scale(0) * get_scale(1));

#pragma unroll
    for (int mi = 0; mi < 4; mi++) {
#pragma unroll
        for (int ni = 0; ni < 8; ni++) {
            int row0 = mBase + wm * 64 + mi * 16 + lg;
            int col  = nBase + wn * 64 + ni * 8 + lt * 2;
            float2 v0, v1;
            v0.x = acc[mi][ni][0] * inv;
            v0.y = acc[mi][ni][1] * inv;
            v1.x = acc[mi][ni][2] * inv;
            v1.y = acc[mi][ni][3] * inv;
            *reinterpret_cast<float2*>(out + (size_t)row0 * NDIM + col) = v0;
            *reinterpret_cast<float2*>(out + (size_t)(row0 + 8) * NDIM + col) = v1;
        }
    }
}

// ---------------- launch ----------------
extern "C" void kernel_launch(void* const* d_in, const int* in_sizes, int n_in,
                              void* d_out, int out_size) {
    const float* lhs = (const float*)d_in[0];
    const float* rhs = (const float*)d_in[1];
    float* out = (float*)d_out;

    cudaFuncSetAttribute(gemm_bf16_kernel,
                         cudaFuncAttributeMaxDynamicSharedMemorySize, GEMM_SMEM);

    // reset amax accumulators (graph-capturable memset node; no kernel launch)
    void* amax_ptr = nullptr;
    cudaGetSymbolAddress(&amax_ptr, g_amax);
    cudaMemsetAsync(amax_ptr, 0, 2 * sizeof(unsigned));

    // fused abs-max over both tensors (1024 blocks per tensor)
    amax2_kernel<<<2048, 256>>>(lhs, rhs, (MDIM * KDIM) / 4);

    // fused quantization of both tensors (4096 blocks per tensor)
    quant2_kernel<<<8192, 256>>>(lhs, rhs);

    dim3 grid(NDIM / 128, MDIM / 256);
    gemm_bf16_kernel<<<grid, 256, GEMM_SMEM>>>(out);
}

// round 17
// speedup vs baseline: 1.0041x; 1.0041x over previous
#include <cuda_runtime.h>
#include <cuda_bf16.h>
#include <cstdint>

#define MDIM 4096
#define NDIM 4096
#define KDIM 4096

// ---------------- device scratch (no allocations allowed) ----------------
__device__ unsigned g_amax[2];                                        // float bits
__device__ __align__(128) unsigned short g_qa[(size_t)MDIM * KDIM];   // lhs quantized ints as bf16, [M][K]
__device__ __align__(128) unsigned short g_qb[(size_t)KDIM * NDIM];   // rhs quantized ints as bf16, [K][N]

// ---------------- calibration ----------------
// One launch covers BOTH tensors: blocks [0, half) -> lhs, [half, 2*half) -> rhs.
// Plain sequential grid-stride: empirically the fastest-coexisting pattern
// (strided/multi-accumulator variants flipped the pipeline into a ~645us regime).
__global__ void amax2_kernel(const float* __restrict__ lhs,
                             const float* __restrict__ rhs, int n4each) {
    const int half = gridDim.x >> 1;
    const int which = blockIdx.x >= half;
    const float* __restrict__ x = which ? rhs : lhs;
    const int bid = blockIdx.x - which * half;

    float m = 0.0f;
    const int stride = half * blockDim.x;
    for (int i = bid * blockDim.x + threadIdx.x; i < n4each; i += stride) {
        float4 v = reinterpret_cast<const float4*>(x)[i];
        m = fmaxf(m, fmaxf(fmaxf(fabsf(v.x), fabsf(v.y)), fmaxf(fabsf(v.z), fabsf(v.w))));
    }
#pragma unroll
    for (int o = 16; o > 0; o >>= 1)
        m = fmaxf(m, __shfl_xor_sync(0xFFFFFFFFu, m, o));
    if ((threadIdx.x & 31) == 0)
        atomicMax(&g_amax[which], __float_as_uint(m));  // m >= 0: uint order == float order
}

__device__ __forceinline__ float get_scale(int which) {
    float amax = __uint_as_float(g_amax[which]);
    return 127.0f / fmaxf(amax, 1e-12f);
}

// quantize to int on the int8 grid, return EXACT bf16 representation (|v|<=127)
__device__ __forceinline__ unsigned short q8_bf16(float x, float s) {
    float r = rintf(x * s);  // round-half-even, matches jnp.round
    r = fmaxf(-127.0f, fminf(127.0f, r));
    return __bfloat16_as_ushort(__float2bfloat16_rn(r));   // ints <=127 exact in bf16
}

// One launch quantizes BOTH tensors; 4 consecutive float4 per thread.
__global__ void quant2_kernel(const float* __restrict__ lhs,
                              const float* __restrict__ rhs) {
    const int half = gridDim.x >> 1;
    const int which = blockIdx.x >= half;
    const float* __restrict__ x = which ? rhs : lhs;
    unsigned short* __restrict__ q = which ? g_qb : g_qa;
    const int bid = blockIdx.x - which * half;

    float s = get_scale(which);
    int base = (bid * blockDim.x + threadIdx.x) * 4;
#pragma unroll
    for (int j = 0; j < 4; j++) {
        int idx = base + j;
        float4 v = reinterpret_cast<const float4*>(x)[idx];
        uint2 o;
        o.x = (uint32_t)q8_bf16(v.x, s) | ((uint32_t)q8_bf16(v.y, s) << 16);
        o.y = (uint32_t)q8_bf16(v.z, s) | ((uint32_t)q8_bf16(v.w, s) << 16);
        reinterpret_cast<uint2*>(q)[idx] = o;
    }
}

// ---------------- bf16 HMMA GEMM ----------------
// CTA tile 256x128 (MxN), K-chunk 64, 4-stage cp.async ring, 8 warps (4Mx2N),
// warp tile 64x64, register-fragment double buffering. Pipe/power-bound at the
// legacy mma.sync HMMA floor for plain-target sm_103.
#define NSTG 4
#define A_ST_BYTES 32768                 // 256 rows * 128B
#define STAGE_BYTES 49152                // A 32KB + B 16KB
#define GEMM_SMEM (NSTG * STAGE_BYTES)   // 196608
#define NC (KDIM / 64)

__device__ __forceinline__ uint32_t smem_u32(const void* p) {
    uint32_t a;
    asm("{ .reg .u64 t; cvta.to.shared.u64 t, %1; cvt.u32.u64 %0, t; }" : "=r"(a) : "l"(p));
    return a;
}

__global__ void __launch_bounds__(256, 1) gemm_bf16_kernel(float* __restrict__ out) {
    extern __shared__ char sm[];
    const uint32_t sb = smem_u32(sm);

    const int tid  = threadIdx.x;
    const int lane = tid & 31;
    const int warp = tid >> 5;
    const int wm = warp & 3;               // 4 warps along M (64 rows each)
    const int wn = warp >> 2;              // 2 warps along N (64 cols each)
    const int lg = lane >> 2;              // groupID
    const int lt = lane & 3;               // threadID in group

    const int mBase = blockIdx.y * 256;
    const int nBase = blockIdx.x * 128;

    float acc[4][8][4];
#pragma unroll
    for (int mi = 0; mi < 4; mi++)
#pragma unroll
        for (int ni = 0; ni < 8; ni++)
#pragma unroll
            for (int r = 0; r < 4; r++) acc[mi][ni][r] = 0.0f;

    const int a_row_in = lane & 15;
    const int a_hi = lane >> 4;

    auto issue = [&](int ch) {
        if (ch < NC) {
            const int kt = ch * 64;
            const uint32_t st = sb + (ch % NSTG) * STAGE_BYTES;
#pragma unroll
            for (int it = 0; it < 8; it++) {
                int c = tid + it * 256;
                int row = c >> 3, cb = c & 7;
                uint32_t dst = st + row * 128 + ((cb ^ (row & 7)) << 4);
                const void* src = g_qa + (size_t)(mBase + row) * KDIM + kt + cb * 8;
                asm volatile("cp.async.cg.shared.global [%0], [%1], 16;"
                             :: "r"(dst), "l"(src) : "memory");
            }
#pragma unroll
            for (int it = 0; it < 4; it++) {
                int c = tid + it * 256;
                int row = c >> 4, cb = c & 15;
                uint32_t dst = st + A_ST_BYTES + row * 256 + ((cb ^ (row & 7)) << 4);
                const void* src = g_qb + (size_t)(kt + row) * NDIM + nBase + cb * 8;
                asm volatile("cp.async.cg.shared.global [%0], [%1], 16;"
                             :: "r"(dst), "l"(src) : "memory");
            }
        }
        asm volatile("cp.async.commit_group;" ::: "memory");
    };

    auto ldA = [&](uint32_t stA, int ks, uint32_t a[4][4]) {
#pragma unroll
        for (int mi = 0; mi < 4; mi++) {
            int row = wm * 64 + mi * 16 + a_row_in;
            int cb  = ks * 2 + a_hi;
            uint32_t addr = stA + row * 128 + ((cb ^ (row & 7)) << 4);
            asm volatile("ldmatrix.sync.aligned.m8n8.x4.shared.b16 {%0,%1,%2,%3}, [%4];"
                         : "=r"(a[mi][0]), "=r"(a[mi][1]), "=r"(a[mi][2]), "=r"(a[mi][3])
                         : "r"(addr));
        }
    };
    auto ldB = [&](uint32_t stB, int ks, uint32_t b[4][4]) {
#pragma unroll
        for (int p = 0; p < 4; p++) {
            int krow = ks * 16 + a_row_in;
            int cb   = (wn * 8 + p * 2) + a_hi;
            uint32_t addr = stB + krow * 256 + ((cb ^ (krow & 7)) << 4);
            asm volatile("ldmatrix.sync.aligned.m8n8.x4.trans.shared.b16 {%0,%1,%2,%3}, [%4];"
                         : "=r"(b[p][0]), "=r"(b[p][1]), "=r"(b[p][2]), "=r"(b[p][3])
                         : "r"(addr));
        }
    };

    issue(0); issue(1); issue(2);

    uint32_t afrag[2][4][4], bfrag[2][4][4];

    for (int ch = 0; ch < NC; ch++) {
        asm volatile("cp.async.wait_group 2;" ::: "memory");
        __syncthreads();
        issue(ch + 3);

        const uint32_t stA = sb + (ch % NSTG) * STAGE_BYTES;
        const uint32_t stB = stA + A_ST_BYTES;

        ldA(stA, 0, afrag[0]);
        ldB(stB, 0, bfrag[0]);

#pragma unroll
        for (int ks = 0; ks < 4; ks++) {
            const int cur = ks & 1, nxt = cur ^ 1;
            if (ks < 3) {
                ldA(stA, ks + 1, afrag[nxt]);
                ldB(stB, ks + 1, bfrag[nxt]);
            }
#pragma unroll
            for (int p = 0; p < 4; p++) {
#pragma unroll
                for (int h = 0; h < 2; h++) {
                    int ni = p * 2 + h;
#pragma unroll
                    for (int mi = 0; mi < 4; mi++) {
                        asm volatile(
                            "mma.sync.aligned.m16n8k16.row.col.f32.bf16.bf16.f32 "
                            "{%0,%1,%2,%3}, {%4,%5,%6,%7}, {%8,%9}, {%0,%1,%2,%3};\n"
                            : "+f"(acc[mi][ni][0]), "+f"(acc[mi][ni][1]),
                              "+f"(acc[mi][ni][2]), "+f"(acc[mi][ni][3])
                            : "r"(afrag[cur][mi][0]), "r"(afrag[cur][mi][1]),
                              "r"(afrag[cur][mi][2]), "r"(afrag[cur][mi][3]),
                              "r"(bfrag[cur][p][2 * h]), "r"(bfrag[cur][p][2 * h + 1]));
                    }
                }
            }
        }
    }

    // ---------------- epilogue: exact fp32 dequant ----------------
    float inv = 1.0f / (get_scale(0) * get_scale(1));

#pragma unroll
    for (int mi = 0; mi < 4; mi++) {
#pragma unroll
        for (int ni = 0; ni < 8; ni++) {
            int row0 = mBase + wm * 64 + mi * 16 + lg;
            int col  = nBase + wn * 64 + ni * 8 + lt * 2;
            float2 v0, v1;
            v0.x = acc[mi][ni][0] * inv;
            v0.y = acc[mi][ni][1] * inv;
            v1.x = acc[mi][ni][2] * inv;
            v1.y = acc[mi][ni][3] * inv;
            *reinterpret_cast<float2*>(out + (size_t)row0 * NDIM + col) = v0;
            *reinterpret_cast<float2*>(out + (size_t)(row0 + 8) * NDIM + col) = v1;
        }
    }
}

// ---------------- launch ----------------
extern "C" void kernel_launch(void* const* d_in, const int* in_sizes, int n_in,
                              void* d_out, int out_size) {
    const float* lhs = (const float*)d_in[0];
    const float* rhs = (const float*)d_in[1];
    float* out = (float*)d_out;

    cudaFuncSetAttribute(gemm_bf16_kernel,
                         cudaFuncAttributeMaxDynamicSharedMemorySize, GEMM_SMEM);

    // reset amax accumulators (graph-capturable memset node; no kernel launch)
    void* amax_ptr = nullptr;
    cudaGetSymbolAddress(&amax_ptr, g_amax);
    cudaMemsetAsync(amax_ptr, 0, 2 * sizeof(unsigned));

    // fused abs-max over both tensors (1024 blocks per tensor)
    amax2_kernel<<<2048, 256>>>(lhs, rhs, (MDIM * KDIM) / 4);

    // fused quantization of both tensors (4096 blocks per tensor)
    quant2_kernel<<<8192, 256>>>(lhs, rhs);

    dim3 grid(NDIM / 128, MDIM / 256);
    gemm_bf16_kernel<<<grid, 256, GEMM_SMEM>>>(out);
}